// round 16
// baseline (speedup 1.0000x reference)
#include <cuda_runtime.h>
#include <cuda_bf16.h>
#include <mma.h>
#include <math.h>

using namespace nvcuda;

#define Nn 50000
#define Ee 800000
#define Dd 128
#define Gg 500
#define NSs 100
#define M0 64
#define SLOPE 0.2f
#define BN_EPS 1e-5f
#define PADB 136              // bf16 elements per smem row (272B -> 4-bank shift)
#define PADE 68               // f32 epilogue staging stride

#define SCAN_BLK 512
#define SCAN_NB ((Nn + SCAN_BLK - 1) / SCAN_BLK)   // 98

// -------- scratch (device globals; no allocation allowed) --------
// NEVER pass these names from host code directly (host shadow + ATS trap);
// always cudaGetSymbolAddress.
__device__ uint2 g_xlb[Nn * 32];        // xl in bf16 (4 values / uint2 / lane)
__device__ float g_xr[Nn * Dd];
__device__ float g_h1[Nn * Dd];
__device__ float g_h2[Nn * Dd];
__device__ float g_pooled[Gg * Dd];
__device__ __nv_bfloat16 g_wb[4 * Dd * Dd];   // bf16 wl0,wr0,wl1,wr1
__device__ float g_brep[4 * 16 * Dd];         // bias rows replicated 16x
__device__ int   g_src[Ee];
__device__ int   g_dst[Ee];
__device__ int   g_counts[Nn];
__device__ int   g_incl[Nn];
__device__ int   g_rowPtr[Nn + 1];
__device__ int   g_head[Nn];
__device__ int   g_csr_src[Ee];
__device__ int   g_blockSums[SCAN_NB + 8];
__device__ int   g_blockOff[SCAN_NB + 8];
__device__ int   g_gcounts[Gg];
__device__ int   g_gstart[Gg + 1];

// ---------------- side stream + fork/join events (static init: before harness
// memory checkpoints; no device-memory allocation APIs involved) --------------
struct Sess {
    cudaStream_t s2;
    cudaEvent_t evF, evJ;
    Sess() {
        cudaStreamCreateWithFlags(&s2, cudaStreamNonBlocking);
        cudaEventCreateWithFlags(&evF, cudaEventDisableTiming);
        cudaEventCreateWithFlags(&evJ, cudaEventDisableTiming);
    }
};
static Sess g_sess;

// ---------------- weight/bias pre-convert (main stream, before GEMM0) -----------
__global__ void k_wconv(const float* __restrict__ wl0, const float* __restrict__ wr0,
                        const float* __restrict__ wl1, const float* __restrict__ wr1,
                        const float* __restrict__ bl0, const float* __restrict__ br0,
                        const float* __restrict__ bl1, const float* __restrict__ br1) {
    int i = blockIdx.x * blockDim.x + threadIdx.x;
    if (i < 4 * Dd * Dd) {
        const float* ws[4] = {wl0, wr0, wl1, wr1};
        g_wb[i] = __float2bfloat16(ws[i >> 14][i & (Dd * Dd - 1)]);
    }
    if (i < 4 * 16 * Dd) {
        const float* bs[4] = {bl0, br0, bl1, br1};
        g_brep[i] = bs[i >> 11][i & (Dd - 1)];
    }
}

// ---------------- zero (must precede decode+hist atomics) ----------------
__global__ void k_zero() {
    int i = blockIdx.x * blockDim.x + threadIdx.x;
    if (i < Nn) g_counts[i] = 0;
    if (i < Gg) g_gcounts[i] = 0;
}

// ---------------- decode + both histograms ----------------
__global__ void k_decode_hist(const int* __restrict__ gd, const int* __restrict__ batch) {
    int i = blockIdx.x * blockDim.x + threadIdx.x;
    if (i < Nn) atomicAdd(&g_gcounts[batch[i]], 1);
    if (i >= Ee) return;
    bool w64 = (gd[1] == 0 && gd[3] == 0 && gd[5] == 0 && gd[7] == 0);
    int s, d;
    if (w64) { s = gd[2 * i]; d = gd[2 * Ee + 2 * i]; }
    else     { s = gd[i];     d = gd[Ee + i]; }
    g_src[i] = s;
    g_dst[i] = d;
    atomicAdd(&g_counts[d], 1);
}

// ---------------- scans ----------------
__global__ void k_scan1() {
    __shared__ int s[SCAN_BLK];
    int tid = threadIdx.x;
    int i = blockIdx.x * SCAN_BLK + tid;
    int v = (i < Nn) ? g_counts[i] : 0;
    s[tid] = v;
    __syncthreads();
    for (int off = 1; off < SCAN_BLK; off <<= 1) {
        int add = (tid >= off) ? s[tid - off] : 0;
        __syncthreads();
        s[tid] += add;
        __syncthreads();
    }
    if (i < Nn) g_incl[i] = s[tid];
    if (tid == SCAN_BLK - 1) g_blockSums[blockIdx.x] = s[tid];
}
__global__ void k_scan2p() {
    __shared__ int s[512];
    int t = threadIdx.x;
    int v = (t < SCAN_NB) ? g_blockSums[t] : 0;
    s[t] = v;
    __syncthreads();
    for (int off = 1; off < 512; off <<= 1) {
        int a = (t >= off) ? s[t - off] : 0;
        __syncthreads();
        s[t] += a;
        __syncthreads();
    }
    if (t < SCAN_NB) g_blockOff[t] = s[t] - v;
    __syncthreads();
    int w = (t < Gg) ? g_gcounts[t] : 0;
    s[t] = w;
    __syncthreads();
    for (int off = 1; off < 512; off <<= 1) {
        int a = (t >= off) ? s[t - off] : 0;
        __syncthreads();
        s[t] += a;
        __syncthreads();
    }
    if (t < Gg) g_gstart[t] = s[t] - w;
    if (t == Gg - 1) g_gstart[Gg] = s[t];
}
__global__ void k_scan3() {
    int i = blockIdx.x * blockDim.x + threadIdx.x;
    if (i < Nn) {
        int tot = g_incl[i] + g_blockOff[i / SCAN_BLK];
        int excl = tot - g_counts[i];
        g_rowPtr[i] = excl;
        g_head[i] = excl;
        if (i == Nn - 1) g_rowPtr[Nn] = tot;
    }
}
__global__ void k_fill() {
    int i = blockIdx.x * blockDim.x + threadIdx.x;
    if (i < Ee) {
        int pos = atomicAdd(&g_head[g_dst[i]], 1);
        g_csr_src[pos] = g_src[i];
    }
}

// ---------------- dual GEMM (bf16 m16n16k16), 64x64 warp tiles -------------------
__global__ void __launch_bounds__(128, 2)
k_gemm_dual(const float* __restrict__ A, float* __restrict__ Cxr,
            uint2* __restrict__ Cxl, int nrows, int layer) {
    extern __shared__ char smc[];
    __nv_bfloat16* sA = (__nv_bfloat16*)smc;              // 128 x PADB bf16
    __nv_bfloat16* sB = (__nv_bfloat16*)(smc + 128 * PADB * 2);  // 32 x PADB bf16
    float* sE = (float*)(smc + 128 * PADB * 2);           // union: 128 x PADE f32
    int tid = threadIdx.x;                   // 0..127
    int wid = tid >> 5;                      // 0..3
    int warp_m = wid >> 1;                   // 0..1 (64-row band)
    int warp_n = wid & 1;                    // 0..1 (64-col half)
    int rowBase = blockIdx.x * 128;

    // stage A once, f32 -> bf16
#pragma unroll 8
    for (int i = 0; i < 32; i++) {
        int idx = tid + i * 128;             // 0..4095
        int r = idx >> 5, c4 = idx & 31;
        int gr = rowBase + r;
        float4 v = make_float4(0.f, 0.f, 0.f, 0.f);
        if (gr < nrows) v = *(const float4*)(A + gr * 128 + c4 * 4);
        __nv_bfloat162 b0 = __float22bfloat162_rn(make_float2(v.x, v.y));
        __nv_bfloat162 b1 = __float22bfloat162_rn(make_float2(v.z, v.w));
        uint2 u;
        u.x = *reinterpret_cast<unsigned*>(&b0);
        u.y = *reinterpret_cast<unsigned*>(&b1);
        *reinterpret_cast<uint2*>(sA + r * PADB + c4 * 4) = u;
    }

#pragma unroll
    for (int w = 0; w < 2; w++) {
        int widx = layer * 2 + (w == 0 ? 1 : 0);   // w=0 -> xr(wr), w=1 -> xl(wl)
        const __nv_bfloat16* Wp = g_wb + widx * Dd * Dd;
        const float* Bp = g_brep + widx * 16 * Dd;

        wmma::fragment<wmma::accumulator, 16, 16, 16, float> acc[4][4];
#pragma unroll
        for (int i = 0; i < 4; i++)
#pragma unroll
            for (int j = 0; j < 4; j++)
                wmma::load_matrix_sync(acc[i][j], Bp + warp_n * 64 + j * 16, 128,
                                       wmma::mem_row_major);

        for (int k0 = 0; k0 < 128; k0 += 32) {
            __syncthreads();
#pragma unroll
            for (int i = 0; i < 4; i++) {
                int u = tid + i * 128;        // 0..511 (16B units: 8 bf16)
                int r = u >> 4, cu = u & 15;
                *reinterpret_cast<uint4*>(sB + r * PADB + cu * 8) =
                    *reinterpret_cast<const uint4*>(Wp + (k0 + r) * 128 + cu * 8);
            }
            __syncthreads();
#pragma unroll
            for (int kk = 0; kk < 32; kk += 16) {
                wmma::fragment<wmma::matrix_a, 16, 16, 16, __nv_bfloat16, wmma::row_major> af[4];
                wmma::fragment<wmma::matrix_b, 16, 16, 16, __nv_bfloat16, wmma::row_major> bf[4];
#pragma unroll
                for (int i = 0; i < 4; i++)
                    wmma::load_matrix_sync(af[i], sA + (warp_m * 64 + i * 16) * PADB + k0 + kk, PADB);
#pragma unroll
                for (int j = 0; j < 4; j++)
                    wmma::load_matrix_sync(bf[j], sB + kk * PADB + warp_n * 64 + j * 16, PADB);
#pragma unroll
                for (int i = 0; i < 4; i++)
#pragma unroll
                    for (int j = 0; j < 4; j++)
                        wmma::mma_sync(acc[i][j], af[i], bf[j], acc[i][j]);
            }
        }

        if (w == 0) {
#pragma unroll
            for (int i = 0; i < 4; i++) {
                int r0 = rowBase + warp_m * 64 + i * 16;
                if (r0 < nrows) {
                    float* base = Cxr + r0 * 128 + warp_n * 64;
#pragma unroll
                    for (int j = 0; j < 4; j++)
                        wmma::store_matrix_sync(base + j * 16, acc[i][j], 128,
                                                wmma::mem_row_major);
                }
            }
        } else {
#pragma unroll
            for (int half = 0; half < 2; half++) {
                __syncthreads();
                if (warp_n == half) {
#pragma unroll
                    for (int i = 0; i < 4; i++) {
                        float* base = sE + (warp_m * 64 + i * 16) * PADE;
#pragma unroll
                        for (int j = 0; j < 4; j++)
                            wmma::store_matrix_sync(base + j * 16, acc[i][j], PADE,
                                                    wmma::mem_row_major);
                    }
                }
                __syncthreads();
#pragma unroll
                for (int i = 0; i < 16; i++) {
                    int idx = tid + i * 128;      // 0..2047 (float4 units, 128x16)
                    int r = idx >> 4, c = idx & 15;
                    int gr = rowBase + r;
                    if (gr < nrows) {
                        float4 v = *(float4*)(sE + r * PADE + c * 4);
                        __nv_bfloat162 b0 = __float22bfloat162_rn(make_float2(v.x, v.y));
                        __nv_bfloat162 b1 = __float22bfloat162_rn(make_float2(v.z, v.w));
                        uint2 u;
                        u.x = *reinterpret_cast<unsigned*>(&b0);
                        u.y = *reinterpret_cast<unsigned*>(&b1);
                        Cxl[gr * 32 + half * 16 + c] = u;
                    }
                }
            }
        }
    }
}

// ---------------- GATv2 aggregate: no-max softmax, 8-edge pipeline ------------------
__device__ __forceinline__ float4 bf2f4(uint2 u) {
    __nv_bfloat162 b0 = *reinterpret_cast<__nv_bfloat162*>(&u.x);
    __nv_bfloat162 b1 = *reinterpret_cast<__nv_bfloat162*>(&u.y);
    float2 f0 = __bfloat1622float2(b0);
    float2 f1 = __bfloat1622float2(b1);
    return make_float4(f0.x, f0.y, f1.x, f1.y);
}
__device__ __forceinline__ float edge_partial(float4 r, float4 xrv, float4 attv) {
    float vx = r.x + xrv.x, vy = r.y + xrv.y, vz = r.z + xrv.z, vw = r.w + xrv.w;
    vx = vx > 0.f ? vx : SLOPE * vx;
    vy = vy > 0.f ? vy : SLOPE * vy;
    vz = vz > 0.f ? vz : SLOPE * vz;
    vw = vw > 0.f ? vw : SLOPE * vw;
    return vx * attv.x + vy * attv.y + vz * attv.z + vw * attv.w;
}
__global__ void k_aggregate(const uint2* __restrict__ xlb, const float4* __restrict__ xr,
                            const float4* __restrict__ att, const float4* __restrict__ bias,
                            float4* __restrict__ out,
                            int do_bn,
                            const float4* __restrict__ gamma, const float4* __restrict__ beta,
                            const float4* __restrict__ mean, const float4* __restrict__ var) {
    int warpId = (blockIdx.x * blockDim.x + threadIdx.x) >> 5;
    if (warpId >= Nn) return;
    int lane = threadIdx.x & 31;
    int d = warpId;
    int s0 = g_rowPtr[d], s1 = g_rowPtr[d + 1];

    float4 xrv = xr[d * 32 + lane];
    float4 attv = att[lane];

    // unshifted softmax (logits bounded); 4 independent accumulator chains
    float den0 = 0.f, den1 = 0.f, den2 = 0.f, den3 = 0.f;
    float4 a0 = make_float4(0.f, 0.f, 0.f, 0.f), a1 = a0, a2 = a0, a3 = a0;

    int p = s0;
    for (; p + 8 <= s1; p += 8) {
        uint2 u[8];
#pragma unroll
        for (int j = 0; j < 8; j++) u[j] = xlb[g_csr_src[p + j] * 32 + lane];
        float4 r[8];
        float l[8];
#pragma unroll
        for (int j = 0; j < 8; j++) {
            r[j] = bf2f4(u[j]);
            l[j] = edge_partial(r[j], xrv, attv);
        }
#pragma unroll
        for (int o = 16; o; o >>= 1)
#pragma unroll
            for (int j = 0; j < 8; j++)
                l[j] += __shfl_xor_sync(0xffffffffu, l[j], o);
#pragma unroll
        for (int j = 0; j < 8; j += 4) {
            float p0 = __expf(l[j]), p1 = __expf(l[j + 1]);
            float p2 = __expf(l[j + 2]), p3 = __expf(l[j + 3]);
            den0 += p0; a0.x += p0 * r[j].x;     a0.y += p0 * r[j].y;     a0.z += p0 * r[j].z;     a0.w += p0 * r[j].w;
            den1 += p1; a1.x += p1 * r[j + 1].x; a1.y += p1 * r[j + 1].y; a1.z += p1 * r[j + 1].z; a1.w += p1 * r[j + 1].w;
            den2 += p2; a2.x += p2 * r[j + 2].x; a2.y += p2 * r[j + 2].y; a2.z += p2 * r[j + 2].z; a2.w += p2 * r[j + 2].w;
            den3 += p3; a3.x += p3 * r[j + 3].x; a3.y += p3 * r[j + 3].y; a3.z += p3 * r[j + 3].z; a3.w += p3 * r[j + 3].w;
        }
    }
    for (; p + 4 <= s1; p += 4) {
        float4 r0 = bf2f4(xlb[g_csr_src[p] * 32 + lane]);
        float4 r1 = bf2f4(xlb[g_csr_src[p + 1] * 32 + lane]);
        float4 r2 = bf2f4(xlb[g_csr_src[p + 2] * 32 + lane]);
        float4 r3 = bf2f4(xlb[g_csr_src[p + 3] * 32 + lane]);
        float l0 = edge_partial(r0, xrv, attv);
        float l1 = edge_partial(r1, xrv, attv);
        float l2 = edge_partial(r2, xrv, attv);
        float l3 = edge_partial(r3, xrv, attv);
#pragma unroll
        for (int o = 16; o; o >>= 1) {
            l0 += __shfl_xor_sync(0xffffffffu, l0, o);
            l1 += __shfl_xor_sync(0xffffffffu, l1, o);
            l2 += __shfl_xor_sync(0xffffffffu, l2, o);
            l3 += __shfl_xor_sync(0xffffffffu, l3, o);
        }
        float p0 = __expf(l0), p1 = __expf(l1), p2 = __expf(l2), p3 = __expf(l3);
        den0 += p0; a0.x += p0 * r0.x; a0.y += p0 * r0.y; a0.z += p0 * r0.z; a0.w += p0 * r0.w;
        den1 += p1; a1.x += p1 * r1.x; a1.y += p1 * r1.y; a1.z += p1 * r1.z; a1.w += p1 * r1.w;
        den2 += p2; a2.x += p2 * r2.x; a2.y += p2 * r2.y; a2.z += p2 * r2.z; a2.w += p2 * r2.w;
        den3 += p3; a3.x += p3 * r3.x; a3.y += p3 * r3.y; a3.z += p3 * r3.z; a3.w += p3 * r3.w;
    }
    for (; p < s1; p++) {
        float4 r0 = bf2f4(xlb[g_csr_src[p] * 32 + lane]);
        float l0 = edge_partial(r0, xrv, attv);
#pragma unroll
        for (int o = 16; o; o >>= 1) l0 += __shfl_xor_sync(0xffffffffu, l0, o);
        float p0 = __expf(l0);
        den0 += p0; a0.x += p0 * r0.x; a0.y += p0 * r0.y; a0.z += p0 * r0.z; a0.w += p0 * r0.w;
    }

    float denom = (den0 + den1) + (den2 + den3);
    float4 acc;
    acc.x = (a0.x + a1.x) + (a2.x + a3.x);
    acc.y = (a0.y + a1.y) + (a2.y + a3.y);
    acc.z = (a0.z + a1.z) + (a2.z + a3.z);
    acc.w = (a0.w + a1.w) + (a2.w + a3.w);

    float inv = (s1 > s0) ? 1.f / denom : 0.f;
    float4 bv = bias[lane];
    float4 o;
    o.x = acc.x * inv + bv.x;
    o.y = acc.y * inv + bv.y;
    o.z = acc.z * inv + bv.z;
    o.w = acc.w * inv + bv.w;
    if (do_bn) {
        float4 gv = gamma[lane], be = beta[lane], mv = mean[lane], vv = var[lane];
        o.x = fmaxf(gv.x * (o.x - mv.x) * rsqrtf(vv.x + BN_EPS) + be.x, 0.f);
        o.y = fmaxf(gv.y * (o.y - mv.y) * rsqrtf(vv.y + BN_EPS) + be.y, 0.f);
        o.z = fmaxf(gv.z * (o.z - mv.z) * rsqrtf(vv.z + BN_EPS) + be.z, 0.f);
        o.w = fmaxf(gv.w * (o.w - mv.w) * rsqrtf(vv.w + BN_EPS) + be.w, 0.f);
    }
    out[d * 32 + lane] = o;
}

// ---------------- pooling: block per graph (batch is sorted) ----------------
__global__ void k_pool() {
    int g = blockIdx.x;
    int t = threadIdx.x;   // 128
    int s = g_gstart[g], e = g_gstart[g + 1];
    float sum = 0.f;
    for (int r = s; r < e; r++) sum += g_h2[r * 128 + t];
    int cnt = e - s;
    g_pooled[g * 128 + t] = sum / (float)(cnt > 0 ? cnt : 1);
}

// ---------------- fused head: fc1(+bias,relu) tile + fc3 + sigmoid ----------------
__global__ void k_head(const float* __restrict__ fc1w, const float* __restrict__ fc1b,
                       const float* __restrict__ fc3w, const float* __restrict__ fc3b,
                       float* __restrict__ out) {
    __shared__ float As[16][65];
    __shared__ float Bs[16][64];
    __shared__ float red[64][17];
    int t = threadIdx.x;
    int tx = t & 15, ty = t >> 4;
    int g0 = blockIdx.x * 64;
    int s = blockIdx.y;
    int colBase = s * 64;
    float acc[4][4] = {};
    for (int k0 = 0; k0 < 128; k0 += 16) {
#pragma unroll
        for (int i = 0; i < 4; i++) {
            int e = t + i * 256;
            int r = e >> 4, kk = e & 15;
            int gg = g0 + r;
            As[kk][r] = (gg < Gg) ? g_pooled[gg * 128 + k0 + kk] : 0.f;
        }
#pragma unroll
        for (int i = 0; i < 4; i++) {
            int e = t + i * 256;
            int kk = e >> 6, c = e & 63;
            Bs[kk][c] = fc1w[(k0 + kk) * (NSs * M0) + colBase + c];
        }
        __syncthreads();
#pragma unroll
        for (int kk = 0; kk < 16; kk++) {
            float a[4], b[4];
#pragma unroll
            for (int r = 0; r < 4; r++) a[r] = As[kk][ty * 4 + r];
#pragma unroll
            for (int c = 0; c < 4; c++) b[c] = Bs[kk][tx * 4 + c];
#pragma unroll
            for (int r = 0; r < 4; r++)
#pragma unroll
                for (int c = 0; c < 4; c++) acc[r][c] += a[r] * b[c];
        }
        __syncthreads();
    }
#pragma unroll
    for (int r = 0; r < 4; r++) {
        float p = 0.f;
#pragma unroll
        for (int c = 0; c < 4; c++) {
            int j = tx * 4 + c;
            float v = acc[r][c] + fc1b[colBase + j];
            v = fmaxf(v, 0.f);
            p += v * fc3w[j];
        }
        red[ty * 4 + r][tx] = p;
    }
    __syncthreads();
    if (t < 64) {
        float v = 0.f;
#pragma unroll
        for (int i = 0; i < 16; i++) v += red[t][i];
        v += fc3b[0];
        float o = 1.f / (1.f + expf(-v));
        int g = g0 + t;
        if (g < Gg) out[g * NSs + s] = o;
    }
}

// ---------------- launch ----------------
extern "C" void kernel_launch(void* const* d_in, const int* in_sizes, int n_in,
                              void* d_out, int out_size) {
    const float* x     = (const float*)d_in[0];
    const int*   gd    = (const int*)d_in[1];
    const int*   batch = (const int*)d_in[2];
    const float* wl0   = (const float*)d_in[3];
    const float* bl0   = (const float*)d_in[4];
    const float* wr0   = (const float*)d_in[5];
    const float* br0   = (const float*)d_in[6];
    const float* att0  = (const float*)d_in[7];
    const float* b0    = (const float*)d_in[8];
    const float* wl1   = (const float*)d_in[9];
    const float* bl1   = (const float*)d_in[10];
    const float* wr1   = (const float*)d_in[11];
    const float* br1   = (const float*)d_in[12];
    const float* att1  = (const float*)d_in[13];
    const float* b1    = (const float*)d_in[14];
    const float* bn_g  = (const float*)d_in[15];
    const float* bn_b  = (const float*)d_in[16];
    const float* bn_m  = (const float*)d_in[17];
    const float* bn_v  = (const float*)d_in[18];
    const float* fc1w  = (const float*)d_in[19];
    const float* fc1b  = (const float*)d_in[20];
    const float* fc3w  = (const float*)d_in[21];
    const float* fc3b  = (const float*)d_in[22];
    float* out = (float*)d_out;

    // real device addresses (NOT the host shadow symbols)
    uint2 *p_xlb;
    float *p_xr, *p_h1, *p_h2;
    cudaGetSymbolAddress((void**)&p_xlb, g_xlb);
    cudaGetSymbolAddress((void**)&p_xr, g_xr);
    cudaGetSymbolAddress((void**)&p_h1, g_h1);
    cudaGetSymbolAddress((void**)&p_h2, g_h2);

    const int GEMM_SMEM = 128 * PADB * 2 + 128 * PADE * 4;   // 69632 B
    cudaFuncSetAttribute(k_gemm_dual,
                         cudaFuncAttributeMaxDynamicSharedMemorySize, GEMM_SMEM);

    const int GB = (Nn + 127) / 128;   // 391
    cudaStream_t s2 = g_sess.s2;

    // fork: CSR chain (side stream) runs concurrently with wconv+GEMM0 (main)
    cudaEventRecord(g_sess.evF, 0);
    cudaStreamWaitEvent(s2, g_sess.evF, 0);

    // main stream: weight convert + GEMM layer 0
    k_wconv<<<256, 256>>>(wl0, wr0, wl1, wr1, bl0, br0, bl1, br1);        // 0
    k_gemm_dual<<<GB, 128, GEMM_SMEM>>>(x, p_xr, p_xlb, Nn, 0);           // 1

    // side stream: CSR build + graph ranges
    k_zero<<<(Nn + 255) / 256, 256, 0, s2>>>();                           // 2
    k_decode_hist<<<(Ee + 255) / 256, 256, 0, s2>>>(gd, batch);           // 3 <- profiled
    k_scan1<<<SCAN_NB, SCAN_BLK, 0, s2>>>();                              // 4
    k_scan2p<<<1, 512, 0, s2>>>();                                        // 5
    k_scan3<<<(Nn + 255) / 256, 256, 0, s2>>>();                          // 6
    k_fill<<<(Ee + 255) / 256, 256, 0, s2>>>();                           // 7
    cudaEventRecord(g_sess.evJ, s2);

    // join: aggregate needs both branches
    cudaStreamWaitEvent(0, g_sess.evJ, 0);
    k_aggregate<<<(Nn * 32 + 255) / 256, 256>>>(                          // 8
        p_xlb, (const float4*)p_xr,
        (const float4*)att0, (const float4*)b0, (float4*)p_h1,
        1, (const float4*)bn_g, (const float4*)bn_b,
        (const float4*)bn_m, (const float4*)bn_v);
    k_gemm_dual<<<GB, 128, GEMM_SMEM>>>(p_h1, p_xr, p_xlb, Nn, 1);        // 9
    k_aggregate<<<(Nn * 32 + 255) / 256, 256>>>(                          // 10
        p_xlb, (const float4*)p_xr,
        (const float4*)att1, (const float4*)b1, (float4*)p_h2,
        0, (const float4*)0, (const float4*)0,
        (const float4*)0, (const float4*)0);
    k_pool<<<Gg, 128>>>();                                                // 11
    dim3 hgrid((Gg + 63) / 64, NSs);
    k_head<<<hgrid, 256>>>(fc1w, fc1b, fc3w, fc3b, out);                  // 12
    (void)in_sizes; (void)n_in; (void)out_size;
}